// round 16
// baseline (speedup 1.0000x reference)
#include <cuda_runtime.h>
#include <cstdint>

// Shapes (fixed by the problem)
#define B 8
#define N 256
#define IN 64
#define F 64          // H*D
#define H 8
#define NPROD 128     // producer CTAs (K/V): 16 rows each
#define PPB 16        // producers per batch
#define NCTA (B * N)  // 2048 CTAs, one row each

#define L2E 1.4426950408889634f
#define M2C (20.0f * 1.4426950408889634f)   // fixed softmax shift (log2 domain)

typedef unsigned long long ull;

// ---- packed f32x2 helpers (sm_103a FFMA2/FADD2/FMUL2 only via PTX) ----
__device__ __forceinline__ ull pack2(float lo, float hi) {
    ull r; asm("mov.b64 %0, {%1, %2};" : "=l"(r) : "f"(lo), "f"(hi)); return r;
}
__device__ __forceinline__ void unpack2(ull v, float& lo, float& hi) {
    asm("mov.b64 {%0, %1}, %2;" : "=f"(lo), "=f"(hi) : "l"(v));
}
__device__ __forceinline__ ull fma2(ull a, ull b, ull c) {
    ull d; asm("fma.rn.f32x2 %0, %1, %2, %3;" : "=l"(d) : "l"(a), "l"(b), "l"(c)); return d;
}
__device__ __forceinline__ ull mul2(ull a, ull b) {
    ull d; asm("mul.rn.f32x2 %0, %1, %2;" : "=l"(d) : "l"(a), "l"(b)); return d;
}
__device__ __forceinline__ ull add2(ull a, ull b) {
    ull d; asm("add.rn.f32x2 %0, %1, %2;" : "=l"(d) : "l"(a), "l"(b)); return d;
}
__device__ __forceinline__ float ex2(float x) {
    float y; asm("ex2.approx.ftz.f32 %0, %1;" : "=f"(y) : "f"(x)); return y;
}
// streaming 16B load (evict-first at L1+L2)
__device__ __forceinline__ ulonglong2 ldcs2(const ulonglong2* p) {
    ulonglong2 v;
    asm("ld.global.cs.v2.u64 {%0, %1}, [%2];" : "=l"(v.x), "=l"(v.y) : "l"(p));
    return v;
}

// Scratch (allocation-free rule: __device__ globals)
__device__ float g_K[B * N * F];   // pre-scaled by D^-0.5
__device__ float g_V[B * N * F];
__device__ int   g_done[B];        // per-batch producer counters
__device__ int   g_fin = 0;        // CTAs finished (replay-safe reset)

// ---------------------------------------------------------------------------
// Fused kernel. grid = 2048 CTAs (one row i each), 256 threads = 8 warps.
// CTAs 0..127 first produce K/V (16 rows each, batch = blk>>4).
// Consumer: warp w owns head h=w of row i, fully autonomously:
//  - Q slice (8 floats) by shfl-reduce, pre-scaled by log2e
//  - single stream loop over j (16 steps, lane j-parallelism 16, q=lane&1
//    picks the 16B half of the head's 32B f-slice); qk dot + mask computed
//    inline (K from L1/L2); e_att/e_value depth-2 ldcs pipeline; V depth-1
//  - final reduce over j by shfl-xor; lanes 0,1 write the two float4s
// NO __syncthreads in the consumer path.
// ---------------------------------------------------------------------------
__global__ void __launch_bounds__(256, 4) fused_kernel(
    const float* __restrict__ h,
    const float* __restrict__ e_att,
    const float* __restrict__ e_value,
    const uint32_t* __restrict__ attn_mask,   // 4-byte elems; true <=> nonzero
    const float* __restrict__ Wq,
    const float* __restrict__ Wk,
    const float* __restrict__ Wv,
    float* __restrict__ out)
{
    __shared__ float hs[16][IN];   // 4 KB, producer stage only

    const int blk  = blockIdx.x;
    const int b    = blk >> 8;     // batch
    const int i    = blk & 255;    // row
    const int tid  = threadIdx.x;
    const int wid  = tid >> 5;     // head
    const int lane = tid & 31;

    // ================= producer: K/V projection (CTAs 0..127) ===============
    if (blk < NPROD) {
        const int f    = tid & 63;
        const int rq   = tid >> 6;    // 0..3
        const int row0 = blk * 16;

        for (int t = tid; t < 16 * IN; t += 256)
            ((float*)hs)[t] = h[row0 * IN + t];
        __syncthreads();

        float ak[4] = {0, 0, 0, 0}, av[4] = {0, 0, 0, 0};
#pragma unroll 8
        for (int k = 0; k < IN; k++) {
            float wk = Wk[k * F + f];
            float wv = Wv[k * F + f];
#pragma unroll
            for (int rr = 0; rr < 4; rr++) {
                float hv = hs[rq + 4 * rr][k];
                ak[rr] = fmaf(hv, wk, ak[rr]);
                av[rr] = fmaf(hv, wv, av[rr]);
            }
        }
#pragma unroll
        for (int rr = 0; rr < 4; rr++) {
            int row = row0 + rq + 4 * rr;
            g_K[row * F + f] = ak[rr] * 0.35355339059327373f;  // D^-0.5
            g_V[row * F + f] = av[rr];
        }
        __threadfence();
        __syncthreads();
        if (tid == 0) atomicAdd(&g_done[blk >> 4], 1);
    }

    // ======================= consumer (warp-autonomous) =====================
    const int hh  = wid;           // head index
    const int j16 = lane >> 1;     // 0..15: j residue
    const int q   = lane & 1;      // which 16B half of the head's 32B slice

    // ---- Q slice for (i, hh): Qf[f] = L2E * dot(h[i,:], Wq[:, hh*8+f]) ----
    const float* hrow = h + (size_t)(b * N + i) * IN;
    const float  h0 = hrow[2 * lane];
    const float  h1 = hrow[2 * lane + 1];
    float Qf[8];
#pragma unroll
    for (int f = 0; f < 8; f++) {
        const float* wq = Wq + hh * 8 + f;
        float acc = fmaf(h1, wq[(2 * lane + 1) * F], h0 * wq[(2 * lane) * F]);
#pragma unroll
        for (int o = 16; o; o >>= 1) acc += __shfl_xor_sync(0xffffffffu, acc, o);
        Qf[f] = acc * L2E;
    }
    const ull qf01 = pack2(Qf[0], Qf[1]);
    const ull qf23 = pack2(Qf[2], Qf[3]);
    const ull qf45 = pack2(Qf[4], Qf[5]);
    const ull qf67 = pack2(Qf[6], Qf[7]);

    // ---- wait for this batch's K/V (per-warp spin, no CTA barrier) ----
    if (lane == 0) {
        while (*(volatile int*)&g_done[b] < PPB) __nanosleep(32);
    }
    __syncwarp();
    __threadfence();   // order g_K/g_V reads after the flag

    // ---- stream loop: j = j16 + 16*k, k = 0..15 ----
    const ulonglong2* pea = (const ulonglong2*)e_att   + (size_t)(b * N + i) * N * 16;
    const ulonglong2* pev = (const ulonglong2*)e_value + (size_t)(b * N + i) * N * 16;
    const ulonglong2* pK  = (const ulonglong2*)g_K + (size_t)b * N * 16;
    const ulonglong2* pV  = (const ulonglong2*)g_V + (size_t)b * N * 16;
    const uint32_t*   pm  = attn_mask + (size_t)(b * N + i) * N;

    const int idx0 = j16 * 16 + hh * 2 + q;   // 16B-unit index of (j16, f-slice)
    const ull L2E2 = pack2(L2E, L2E);

    ull L01 = 0ull, L23 = 0ull, A01 = 0ull, A23 = 0ull;

    // prime: EA/EV depth-2, V depth-1
    ulonglong2 EA0 = ldcs2(pea + idx0),       EV0 = ldcs2(pev + idx0);
    ulonglong2 EA1 = ldcs2(pea + idx0 + 256), EV1 = ldcs2(pev + idx0 + 256);
    ulonglong2 VV0 = pV[idx0];

#pragma unroll 4
    for (int k = 0; k < 16; k++) {
        const int kp2 = (k + 2 <= 15) ? k + 2 : 15;
        const int kp1 = (k + 1 <= 15) ? k + 1 : 15;
        ulonglong2 EA2 = ldcs2(pea + idx0 + 256 * kp2);
        ulonglong2 EV2 = ldcs2(pev + idx0 + 256 * kp2);
        ulonglong2 VV1 = pV[idx0 + 256 * kp1];

        // inline qk: dot8(Q, K[j]) via f32x2, plus mask fold
        const int kbase = (idx0 - q) + 256 * k;    // K row slice (both halves)
        ulonglong2 ka = pK[kbase];
        ulonglong2 kb = pK[kbase + 1];
        uint32_t   m  = pm[j16 + 16 * k];

        ull s2 = mul2(qf01, ka.x);
        s2 = fma2(qf23, ka.y, s2);
        s2 = fma2(qf45, kb.x, s2);
        s2 = fma2(qf67, kb.y, s2);
        float slo, shi;
        unpack2(s2, slo, shi);
        float qk  = (m != 0u) ? (slo + shi - M2C) : -1e30f;
        ull   qk2 = pack2(qk, qk);

        ull t01 = fma2(EA0.x, L2E2, qk2);
        ull t23 = fma2(EA0.y, L2E2, qk2);
        float f0, f1, f2, f3;
        unpack2(t01, f0, f1);
        unpack2(t23, f2, f3);
        ull p01 = pack2(ex2(f0), ex2(f1));
        ull p23 = pack2(ex2(f2), ex2(f3));

        L01 = add2(L01, p01);
        L23 = add2(L23, p23);
        ull w01 = add2(VV0.x, EV0.x);
        ull w23 = add2(VV0.y, EV0.y);
        A01 = fma2(p01, w01, A01);
        A23 = fma2(p23, w23, A23);

        EA0 = EA1; EV0 = EV1;
        EA1 = EA2; EV1 = EV2;
        VV0 = VV1;
    }

    // ---- reduce over j (lanes with same q): offsets 2,4,8,16 ----
    float l0, l1, l2, l3, a0, a1, a2, a3;
    unpack2(L01, l0, l1);
    unpack2(L23, l2, l3);
    unpack2(A01, a0, a1);
    unpack2(A23, a2, a3);
#pragma unroll
    for (int o = 2; o <= 16; o <<= 1) {
        l0 += __shfl_xor_sync(0xffffffffu, l0, o);
        l1 += __shfl_xor_sync(0xffffffffu, l1, o);
        l2 += __shfl_xor_sync(0xffffffffu, l2, o);
        l3 += __shfl_xor_sync(0xffffffffu, l3, o);
        a0 += __shfl_xor_sync(0xffffffffu, a0, o);
        a1 += __shfl_xor_sync(0xffffffffu, a1, o);
        a2 += __shfl_xor_sync(0xffffffffu, a2, o);
        a3 += __shfl_xor_sync(0xffffffffu, a3, o);
    }

    if (lane < 2) {
        float4 o4;
        o4.x = (l0 > 0.f) ? a0 / l0 : 0.f;
        o4.y = (l1 > 0.f) ? a1 / l1 : 0.f;
        o4.z = (l2 > 0.f) ? a2 / l2 : 0.f;
        o4.w = (l3 > 0.f) ? a3 / l3 : 0.f;
        ((float4*)out)[(size_t)(b * N + i) * 16 + hh * 2 + lane] = o4;
    }

    // ---- replay-safe reset of flags (barrier only here, at the very end) ----
    __syncthreads();
    if (tid == 0) {
        int fin = atomicAdd(&g_fin, 1);
        if (fin == NCTA - 1) {
#pragma unroll
            for (int bb = 0; bb < B; bb++) g_done[bb] = 0;
            g_fin = 0;
            __threadfence();
        }
    }
}

// ---------------------------------------------------------------------------
extern "C" void kernel_launch(void* const* d_in, const int* in_sizes, int n_in,
                              void* d_out, int out_size)
{
    const float*    h       = (const float*)d_in[0];
    const float*    e_att   = (const float*)d_in[1];
    const float*    e_value = (const float*)d_in[2];
    const uint32_t* mask    = (const uint32_t*)d_in[3];
    const float*    Wq      = (const float*)d_in[4];
    const float*    Wk      = (const float*)d_in[5];
    const float*    Wv      = (const float*)d_in[6];
    float*          out     = (float*)d_out;

    fused_kernel<<<NCTA, 256>>>(h, e_att, e_value, mask, Wq, Wk, Wv, out);
}

// round 17
// speedup vs baseline: 2.1235x; 2.1235x over previous
#include <cuda_runtime.h>
#include <cstdint>

// Shapes (fixed by the problem)
#define B 8
#define N 256
#define IN 64
#define F 64          // H*D
#define H 8
#define D 8
#define RPC 2         // rows (i values) per attn item (CTA)
#define NPROD 256     // producer CTAs (K/V): 8 rows each -> 2048 rows
#define PPB 32        // producers per batch

#define L2E 1.4426950408889634f
#define M2C (20.0f * 1.4426950408889634f)   // fixed softmax shift (log2 domain)

typedef unsigned long long ull;

// ---- packed f32x2 helpers (sm_103a FFMA2/FADD2 only reachable via PTX) ----
__device__ __forceinline__ ull pack2(float lo, float hi) {
    ull r; asm("mov.b64 %0, {%1, %2};" : "=l"(r) : "f"(lo), "f"(hi)); return r;
}
__device__ __forceinline__ void unpack2(ull v, float& lo, float& hi) {
    asm("mov.b64 {%0, %1}, %2;" : "=f"(lo), "=f"(hi) : "l"(v));
}
__device__ __forceinline__ ull fma2(ull a, ull b, ull c) {
    ull d; asm("fma.rn.f32x2 %0, %1, %2, %3;" : "=l"(d) : "l"(a), "l"(b), "l"(c)); return d;
}
__device__ __forceinline__ ull add2(ull a, ull b) {
    ull d; asm("add.rn.f32x2 %0, %1, %2;" : "=l"(d) : "l"(a), "l"(b)); return d;
}
__device__ __forceinline__ float ex2(float x) {
    float y; asm("ex2.approx.ftz.f32 %0, %1;" : "=f"(y) : "f"(x)); return y;
}
// streaming 16B load (evict-first at L1+L2)
__device__ __forceinline__ ulonglong2 ldcs2(const ulonglong2* p) {
    ulonglong2 v;
    asm("ld.global.cs.v2.u64 {%0, %1}, [%2];" : "=l"(v.x), "=l"(v.y) : "l"(p));
    return v;
}

// Scratch (allocation-free rule: __device__ globals)
__device__ float g_K[B * N * F];   // pre-scaled by D^-0.5
__device__ float g_V[B * N * F];
__device__ int   g_done[B];        // per-batch producer counters
__device__ int   g_fin = 0;        // CTAs finished (replay-safe reset)

// ---------------------------------------------------------------------------
// Fused kernel. grid = 1024, 256 threads (8 warps), 4 CTAs/SM.
// CTAs 0..255 first produce K/V for 8 rows each (batch = blk>>5), then all
// CTAs run attention for item blk: b = blk>>7, i0 = (blk&127)*2.
// Consumers compute their own Q locally; EA/EV stream primed depth-1 BEFORE
// the producer wait so the first DRAM round-trip overlaps front work.
// Phase 3: f32x2 math, depth-2 reg pipeline on e_att/e_value, depth-1 on V.
// ---------------------------------------------------------------------------
__global__ void __launch_bounds__(256, 4) fused_kernel(
    const float* __restrict__ h,
    const float* __restrict__ e_att,
    const float* __restrict__ e_value,
    const uint32_t* __restrict__ attn_mask,   // 4-byte elems; true <=> nonzero
    const float* __restrict__ Wq,
    const float* __restrict__ Wk,
    const float* __restrict__ Wv,
    float* __restrict__ out)
{
    __shared__ float qk_s[RPC][N][H];    // 16 KB; qk*L2E - M2, or -1e30 masked
    __shared__ float q_s[RPC][F];        // 0.5 KB
    __shared__ float msk_s[RPC][N];      // 2 KB (phase-1 only)
    __shared__ float hrow_s[RPC][IN];    // 0.5 KB (local Q compute)
    __shared__ float part[8][32][9];     // 9 KB (padded): l0..3, a0..3 (reused as hs)

    const int blk  = blockIdx.x;
    const int b    = blk >> 7;           // 128 items per batch
    const int i0   = (blk & 127) * RPC;
    const int tid  = threadIdx.x;
    const int wid  = tid >> 5;           // 0..7
    const int lane = tid & 31;

    // phase-3 mapping (needed early for the prime)
    const int r3 = wid & 1;
    const int jq = wid >> 1;             // 0..3
    const int jo = lane >> 4;            // 0/1
    const int q3 = lane & 15;            // float4 index in f dim
    const int j0 = jq * 64;

    const ulonglong2* pea = (const ulonglong2*)(e_att   + (size_t)(b * N + i0 + r3) * N * F);
    const ulonglong2* pev = (const ulonglong2*)(e_value + (size_t)(b * N + i0 + r3) * N * F);
    const int idx0   = (j0 + jo) * 16 + q3;
    const int idxmax = idx0 + 31 * 32;

    // ---- early prime: first EA/EV step in flight before any front work ----
    ulonglong2 EA0 = ldcs2(pea + idx0);
    ulonglong2 EV0 = ldcs2(pev + idx0);

    // ================= producer: K/V projection (CTAs 0..255) ===============
    if (blk < NPROD) {
        float (*hs)[IN] = (float(*)[IN])&part[0][0][0];   // 8x64 = 2 KB, reused
        const int f    = tid & 63;
        const int rq   = tid >> 6;       // 0..3
        const int row0 = blk * 8;

        for (int t = tid; t < 8 * IN; t += 256)
            ((float*)hs)[t] = h[row0 * IN + t];
        __syncthreads();

        float ak[2] = {0, 0}, av[2] = {0, 0};
#pragma unroll 8
        for (int k = 0; k < IN; k++) {
            float wk = Wk[k * F + f];
            float wv = Wv[k * F + f];
#pragma unroll
            for (int rr = 0; rr < 2; rr++) {
                float hv = hs[rq + 4 * rr][k];
                ak[rr] = fmaf(hv, wk, ak[rr]);
                av[rr] = fmaf(hv, wv, av[rr]);
            }
        }
#pragma unroll
        for (int rr = 0; rr < 2; rr++) {
            int row = row0 + rq + 4 * rr;
            g_K[row * F + f] = ak[rr] * 0.35355339059327373f;  // D^-0.5
            g_V[row * F + f] = av[rr];
        }
        __threadfence();
        __syncthreads();
        if (tid == 0) atomicAdd(&g_done[blk >> 5], 1);
        __syncthreads();   // hs (part) free again before reuse
    }

    // ---- independent work while producers run: mask + local Q ----
    for (int t = tid; t < RPC * N; t += 256) {
        int r = t >> 8, j = t & 255;
        msk_s[r][j] = (attn_mask[(b * N + i0 + r) * N + j] != 0u) ? 1.0f : 0.0f;
    }
    for (int t = tid; t < RPC * IN; t += 256)
        ((float*)hrow_s)[t] = h[(b * N + i0) * IN + t];
    __syncthreads();

    if (tid < RPC * F) {
        const int r = tid >> 6;
        const int f = tid & 63;
        float acc = 0.f;
#pragma unroll 8
        for (int k = 0; k < IN; k++)
            acc = fmaf(hrow_s[r][k], Wq[k * F + f], acc);
        q_s[r][f] = acc;
    }

    // ---- wait for this batch's K/V ----
    if (tid == 0) {
        while (*(volatile int*)&g_done[b] < PPB) __nanosleep(32);
    }
    __syncthreads();
    __threadfence();   // order subsequent g_K/g_V reads after the flag

    // ---- phase 1: qk_s[r][j][h] = mask ? dot8*L2E - M2 : -1e30 ----
    {
        const int hh = lane >> 2;        // 0..7
        const int jm = lane & 3;         // 0..3
        float qreg[RPC][8];
#pragma unroll
        for (int r = 0; r < RPC; r++)
#pragma unroll
            for (int d = 0; d < 8; d++)
                qreg[r][d] = q_s[r][hh * 8 + d];

        const float4* Kb = (const float4*)(g_K + b * N * F);
        for (int jg = wid * 8; jg < wid * 8 + 8; jg++) {
            int j = jm + 4 * jg;
            float4 k0 = Kb[j * 16 + hh * 2];
            float4 k1 = Kb[j * 16 + hh * 2 + 1];
#pragma unroll
            for (int r = 0; r < RPC; r++) {
                float s = qreg[r][0] * k0.x;
                s = fmaf(qreg[r][1], k0.y, s);
                s = fmaf(qreg[r][2], k0.z, s);
                s = fmaf(qreg[r][3], k0.w, s);
                s = fmaf(qreg[r][4], k1.x, s);
                s = fmaf(qreg[r][5], k1.y, s);
                s = fmaf(qreg[r][6], k1.z, s);
                s = fmaf(qreg[r][7], k1.w, s);
                qk_s[r][j][hh] = (msk_s[r][j] != 0.0f) ? fmaf(s, L2E, -M2C)
                                                       : -1e30f;
            }
        }
    }
    __syncthreads();

    // ---- phase 3: streaming softmax + weighted accumulation (64-j slice) ----
    {
        const int hh = q3 >> 1;
        const ulonglong2* pV = (const ulonglong2*)(g_V + b * N * F);

        const ull L2E2 = pack2(L2E, L2E);

        ull L01 = 0ull, L23 = 0ull, A01 = 0ull, A23 = 0ull;

        // finish priming: slot k=1 for EA/EV; k=0 for VV
        ulonglong2 EA1 = ldcs2(pea + idx0 + 32), EV1 = ldcs2(pev + idx0 + 32);
        ulonglong2 VV0 = pV[idx0];

        int idx = idx0;
#pragma unroll 2
        for (int k = 0; k < 32; k++) {
            // prefetch k+2 for DRAM streams, k+1 for V (clamped, in-bounds)
            int idp2 = idx + 64;  idp2 = (idp2 <= idxmax) ? idp2 : idxmax;
            int idp1 = idx + 32;  idp1 = (idp1 <= idxmax) ? idp1 : idxmax;
            ulonglong2 EA2 = ldcs2(pea + idp2);
            ulonglong2 EV2 = ldcs2(pev + idp2);
            ulonglong2 VV1 = pV[idp1];

            float qk  = qk_s[r3][j0 + 2 * k + jo][hh];
            ull   qk2 = pack2(qk, qk);

            ull t01 = fma2(EA0.x, L2E2, qk2);
            ull t23 = fma2(EA0.y, L2E2, qk2);
            float f0, f1, f2, f3;
            unpack2(t01, f0, f1);
            unpack2(t23, f2, f3);
            float p0 = ex2(f0), p1 = ex2(f1), p2 = ex2(f2), p3 = ex2(f3);
            ull p01 = pack2(p0, p1);
            ull p23 = pack2(p2, p3);

            L01 = add2(L01, p01);
            L23 = add2(L23, p23);
            ull w01 = add2(VV0.x, EV0.x);
            ull w23 = add2(VV0.y, EV0.y);
            A01 = fma2(p01, w01, A01);
            A23 = fma2(p23, w23, A23);

            // rotate pipeline registers
            EA0 = EA1; EV0 = EV1;
            EA1 = EA2; EV1 = EV2;
            VV0 = VV1;
            idx = idp1;
        }

        float l0, l1, l2, l3, a0, a1, a2, a3;
        unpack2(L01, l0, l1);
        unpack2(L23, l2, l3);
        unpack2(A01, a0, a1);
        unpack2(A23, a2, a3);

        part[wid][lane][0] = l0;
        part[wid][lane][1] = l1;
        part[wid][lane][2] = l2;
        part[wid][lane][3] = l3;
        part[wid][lane][4] = a0;
        part[wid][lane][5] = a1;
        part[wid][lane][6] = a2;
        part[wid][lane][7] = a3;
    }
    __syncthreads();

    // ---- combine 8 partials per (r, f4) and write out ----
    if (wid < RPC && lane < 16) {
        const int r = wid;
        const int i = i0 + r;
        const int q = lane;
        float L[4] = {0, 0, 0, 0}, A[4] = {0, 0, 0, 0};
#pragma unroll
        for (int w = 0; w < 4; w++) {
            int ww = r + 2 * w;          // warps whose (w&1)==r
#pragma unroll
            for (int c = 0; c < 4; c++) {
                L[c] += part[ww][q][c]     + part[ww][16 + q][c];
                A[c] += part[ww][q][4 + c] + part[ww][16 + q][4 + c];
            }
        }
        float4 o;
        o.x = (L[0] > 0.f) ? A[0] / L[0] : 0.f;
        o.y = (L[1] > 0.f) ? A[1] / L[1] : 0.f;
        o.z = (L[2] > 0.f) ? A[2] / L[2] : 0.f;
        o.w = (L[3] > 0.f) ? A[3] / L[3] : 0.f;
        ((float4*)(out + (size_t)(b * N + i) * F))[q] = o;
    }

    // ---- replay-safe reset of flags (last CTA to finish) ----
    __syncthreads();
    if (tid == 0) {
        int f = atomicAdd(&g_fin, 1);
        if (f == (B * (N / RPC)) - 1) {
#pragma unroll
            for (int bb = 0; bb < B; bb++) g_done[bb] = 0;
            g_fin = 0;
            __threadfence();
        }
    }
}

// ---------------------------------------------------------------------------
extern "C" void kernel_launch(void* const* d_in, const int* in_sizes, int n_in,
                              void* d_out, int out_size)
{
    const float*    h       = (const float*)d_in[0];
    const float*    e_att   = (const float*)d_in[1];
    const float*    e_value = (const float*)d_in[2];
    const uint32_t* mask    = (const uint32_t*)d_in[3];
    const float*    Wq      = (const float*)d_in[4];
    const float*    Wk      = (const float*)d_in[5];
    const float*    Wv      = (const float*)d_in[6];
    float*          out     = (float*)d_out;

    fused_kernel<<<B * (N / RPC), 256>>>(h, e_att, e_value, mask, Wq, Wk, Wv, out);
}